// round 7
// baseline (speedup 1.0000x reference)
#include <cuda_runtime.h>
#include <math.h>
#include <stdint.h>

#define TT    1024
#define DD    2048
#define DFF   1024
#define EE    16
#define KSLOT 6
#define TK    (TT*KSLOT)
#define MAXTILES 64
#define KT    16
#define LDSW  20   // smem row stride (words); 20 mod 32 pattern -> conflict-free frags

// ---------------- scratch (device globals; no allocations allowed) ----------
__device__ int   g_off[EE + 1];
__device__ int   g_tok[TK];
__device__ int   g_slot[TK];
__device__ float g_wt[TK];
__device__ int   g_tile_e[MAXTILES];
__device__ int   g_tile_m0[MAXTILES];
__device__ int   g_ntiles;
__device__ __align__(16) float g_H[(size_t)(TK + 128) * DFF];
__device__ __align__(16) float g_Y[(size_t)TK * DD];

// ---------------- helpers ----------------------------------------------------
__device__ __forceinline__ uint32_t f2tf(float f) {
    uint32_t u;
    asm("cvt.rna.tf32.f32 %0, %1;" : "=r"(u) : "f"(f));
    return u;
}

__device__ __forceinline__ void mma_tf32(float& d0, float& d1, float& d2, float& d3,
                                         uint32_t a0, uint32_t a1, uint32_t a2, uint32_t a3,
                                         uint32_t b0, uint32_t b1) {
    asm volatile(
        "mma.sync.aligned.m16n8k8.row.col.f32.tf32.tf32.f32 "
        "{%0,%1,%2,%3},{%4,%5,%6,%7},{%8,%9},{%0,%1,%2,%3};"
        : "+f"(d0), "+f"(d1), "+f"(d2), "+f"(d3)
        : "r"(a0), "r"(a1), "r"(a2), "r"(a3), "r"(b0), "r"(b1));
}

__device__ __forceinline__ void cp16(void* smem_dst, const void* gmem_src) {
    unsigned d = (unsigned)__cvta_generic_to_shared(smem_dst);
    asm volatile("cp.async.cg.shared.global [%0], [%1], 16;" :: "r"(d), "l"(gmem_src));
}
#define CP_COMMIT() asm volatile("cp.async.commit_group;")
#define CP_WAIT1()  asm volatile("cp.async.wait_group 1;")

__device__ __forceinline__ uint4 tf4(float4 v) {
    return make_uint4(f2tf(v.x), f2tf(v.y), f2tf(v.z), f2tf(v.w));
}

// ---------------- routing: one CTA does count+scan+scatter ------------------
__global__ void k_route(const int* __restrict__ se, const float* __restrict__ rw) {
    __shared__ int cnt[EE], cur[EE], off[EE + 1];
    int tid = threadIdx.x;
    if (tid < EE) { cnt[tid] = 0; cur[tid] = 0; }
    __syncthreads();
    for (int i = tid; i < TK; i += 1024) atomicAdd(&cnt[se[i] & (EE - 1)], 1);
    __syncthreads();
    if (tid == 0) {
        int s = 0, nt = 0;
        off[0] = 0; g_off[0] = 0;
        for (int e = 0; e < EE; e++) {
            int o = s;
            s += cnt[e];
            off[e + 1] = s; g_off[e + 1] = s;
            for (int m0 = o; m0 < s; m0 += 128) {
                g_tile_e[nt] = e; g_tile_m0[nt] = m0; nt++;
            }
        }
        g_ntiles = nt;
    }
    __syncthreads();
    for (int i = tid; i < TK; i += 1024) {
        int e = se[i] & (EE - 1);
        int p = off[e] + atomicAdd(&cur[e], 1);
        g_tok[p]  = i / KSLOT;
        g_slot[p] = i;
        g_wt[p]   = rw[i];
    }
}

// ---------------- pass 1: H = silu(x@w0^T*s0) * (x@w1^T*s1) -----------------
// Block 128(M) x 64(N dff), gate+up; 8 warps = 4(M) x 2(N); warp 32x32 per mat.
// tf32 converted ONCE at STS; register-prefetch double buffer; KT=16.
// Buffer layout (rows of LDSW words): A rows 0-127, Bg rows 128-191, Bu 192-255.
__global__ __launch_bounds__(256, 2)
void k_gateup(const float* __restrict__ x,
              const float* __restrict__ w0,
              const float* __restrict__ w1,
              const float* __restrict__ s0,
              const float* __restrict__ s1) {
    int tile = blockIdx.x;
    if (tile >= g_ntiles) return;
    int e   = g_tile_e[tile];
    int m0  = g_tile_m0[tile];
    int end = g_off[e + 1];
    int n0  = blockIdx.y * 64;

    __shared__ __align__(16) float buf[2][256 * LDSW];
    __shared__ int toks[128];

    int tid = threadIdx.x;
    if (tid < 128) {
        int m = m0 + tid;
        toks[tid] = (m < end) ? g_tok[m] : 0;
    }
    __syncthreads();

    const float* w0e = w0 + (size_t)e * DFF * DD;
    const float* w1e = w1 + (size_t)e * DFF * DD;

    int r4 = tid >> 2, c4 = (tid & 3) * 4;
    float4 va0, va1, vbg, vbu;

    auto ldg = [&](int k0) {
        va0 = *reinterpret_cast<const float4*>(x + (size_t)toks[r4] * DD + k0 + c4);
        va1 = *reinterpret_cast<const float4*>(x + (size_t)toks[r4 + 64] * DD + k0 + c4);
        vbg = *reinterpret_cast<const float4*>(w0e + (size_t)(n0 + r4) * DD + k0 + c4);
        vbu = *reinterpret_cast<const float4*>(w1e + (size_t)(n0 + r4) * DD + k0 + c4);
    };
    auto sts = [&](int s) {
        float* b = buf[s];
        *reinterpret_cast<uint4*>(b + r4 * LDSW + c4)         = tf4(va0);
        *reinterpret_cast<uint4*>(b + (r4 + 64) * LDSW + c4)  = tf4(va1);
        *reinterpret_cast<uint4*>(b + (128 + r4) * LDSW + c4) = tf4(vbg);
        *reinterpret_cast<uint4*>(b + (192 + r4) * LDSW + c4) = tf4(vbu);
    };

    int w  = tid >> 5, L = tid & 31;
    int wm = w & 3, wn = w >> 2;
    int rm = wm * 32, cn = wn * 32;

    float accg[2][4][4] = {}, accu[2][4][4] = {};

    ldg(0);
    sts(0);
    const int NT = DD / KT;   // 128

    for (int it = 0; it < NT; it++) {
        int s = it & 1;
        if (it + 1 < NT) ldg((it + 1) * KT);
        __syncthreads();
        const float* bp = buf[s];

#pragma unroll
        for (int kk = 0; kk < KT; kk += 8) {
            uint32_t a[2][4];
#pragma unroll
            for (int mt = 0; mt < 2; mt++) {
                int r = rm + mt * 16 + (L >> 2);
                int c = kk + (L & 3);
                a[mt][0] = __float_as_uint(bp[r * LDSW + c]);
                a[mt][1] = __float_as_uint(bp[(r + 8) * LDSW + c]);
                a[mt][2] = __float_as_uint(bp[r * LDSW + c + 4]);
                a[mt][3] = __float_as_uint(bp[(r + 8) * LDSW + c + 4]);
            }
#pragma unroll
            for (int nt = 0; nt < 4; nt++) {
                int col = cn + nt * 8 + (L >> 2);
                int c   = kk + (L & 3);
                uint32_t bg0 = __float_as_uint(bp[(128 + col) * LDSW + c]);
                uint32_t bg1 = __float_as_uint(bp[(128 + col) * LDSW + c + 4]);
                uint32_t bu0 = __float_as_uint(bp[(192 + col) * LDSW + c]);
                uint32_t bu1 = __float_as_uint(bp[(192 + col) * LDSW + c + 4]);
#pragma unroll
                for (int mt = 0; mt < 2; mt++) {
                    mma_tf32(accg[mt][nt][0], accg[mt][nt][1], accg[mt][nt][2], accg[mt][nt][3],
                             a[mt][0], a[mt][1], a[mt][2], a[mt][3], bg0, bg1);
                    mma_tf32(accu[mt][nt][0], accu[mt][nt][1], accu[mt][nt][2], accu[mt][nt][3],
                             a[mt][0], a[mt][1], a[mt][2], a[mt][3], bu0, bu1);
                }
            }
        }
        __syncthreads();
        if (it + 1 < NT) sts(s ^ 1);
    }

    // epilogue: SwiGLU; store h pre-rounded to tf32 (replaces pass2's A cvt)
    float sc0 = s0[e], sc1 = s1[e];
#pragma unroll
    for (int mt = 0; mt < 2; mt++) {
#pragma unroll
        for (int half = 0; half < 2; half++) {
            int row = rm + mt * 16 + (L >> 2) + half * 8;
            int m   = m0 + row;
            if (m >= end) continue;
#pragma unroll
            for (int nt = 0; nt < 4; nt++) {
                int col = cn + nt * 8 + (L & 3) * 2;
                float gv0 = accg[mt][nt][half * 2 + 0] * sc0;
                float gv1 = accg[mt][nt][half * 2 + 1] * sc0;
                float uv0 = accu[mt][nt][half * 2 + 0] * sc1;
                float uv1 = accu[mt][nt][half * 2 + 1] * sc1;
                float h0 = (gv0 / (1.f + expf(-gv0))) * uv0;
                float h1 = (gv1 / (1.f + expf(-gv1))) * uv1;
                *reinterpret_cast<float2*>(g_H + (size_t)m * DFF + n0 + col) =
                    make_float2(__uint_as_float(f2tf(h0)), __uint_as_float(f2tf(h1)));
            }
        }
    }
}

// ---------------- pass 2: Y[slot] = wt*s2 * (H @ w2^T) ----------------------
// Block 128x128; 8 warps = 4(M) x 2(N); warp 32x64. A (g_H, pre-rounded tf32)
// via cp.async with NO cvt; B (w2) via reg-prefetch + cvt at STS. KT=16.
// Buffer rows: A 0-127, B 128-255.
__global__ __launch_bounds__(256, 2)
void k_down(const float* __restrict__ w2,
            const float* __restrict__ s2) {
    int tile = blockIdx.x;
    if (tile >= g_ntiles) return;
    int e   = g_tile_e[tile];
    int m0  = g_tile_m0[tile];
    int end = g_off[e + 1];
    int n0  = blockIdx.y * 128;

    __shared__ __align__(16) float buf[2][256 * LDSW];

    int tid = threadIdx.x;
    int r4 = tid >> 2, c4 = (tid & 3) * 4;
    const float* w2e = w2 + (size_t)e * DD * DFF;

    float4 vb0, vb1;
    auto ldgB = [&](int k0) {
        vb0 = *reinterpret_cast<const float4*>(w2e + (size_t)(n0 + r4) * DFF + k0 + c4);
        vb1 = *reinterpret_cast<const float4*>(w2e + (size_t)(n0 + r4 + 64) * DFF + k0 + c4);
    };
    auto cpA = [&](int s, int k0) {
        float* b = buf[s];
        cp16(b + r4 * LDSW + c4,        g_H + (size_t)(m0 + r4) * DFF + k0 + c4);
        cp16(b + (r4 + 64) * LDSW + c4, g_H + (size_t)(m0 + r4 + 64) * DFF + k0 + c4);
    };
    auto stsB = [&](int s) {
        float* b = buf[s];
        *reinterpret_cast<uint4*>(b + (128 + r4) * LDSW + c4) = tf4(vb0);
        *reinterpret_cast<uint4*>(b + (192 + r4) * LDSW + c4) = tf4(vb1);
    };

    int w  = tid >> 5, L = tid & 31;
    int wm = w & 3, wn = w >> 2;
    int rm = wm * 32, cn = wn * 64;

    float acc[2][8][4] = {};

    ldgB(0);
    cpA(0, 0);
    CP_COMMIT();
    stsB(0);
    const int NT = DFF / KT;   // 64

    for (int it = 0; it < NT; it++) {
        int s = it & 1;
        if (it + 1 < NT) { ldgB((it + 1) * KT); cpA(s ^ 1, (it + 1) * KT); }
        CP_COMMIT();
        CP_WAIT1();
        __syncthreads();
        const float* bp = buf[s];

#pragma unroll
        for (int kk = 0; kk < KT; kk += 8) {
            uint32_t a[2][4];
#pragma unroll
            for (int mt = 0; mt < 2; mt++) {
                int r = rm + mt * 16 + (L >> 2);
                int c = kk + (L & 3);
                a[mt][0] = __float_as_uint(bp[r * LDSW + c]);
                a[mt][1] = __float_as_uint(bp[(r + 8) * LDSW + c]);
                a[mt][2] = __float_as_uint(bp[r * LDSW + c + 4]);
                a[mt][3] = __float_as_uint(bp[(r + 8) * LDSW + c + 4]);
            }
#pragma unroll
            for (int nt = 0; nt < 8; nt++) {
                int col = cn + nt * 8 + (L >> 2);
                int c   = kk + (L & 3);
                uint32_t b0 = __float_as_uint(bp[(128 + col) * LDSW + c]);
                uint32_t b1 = __float_as_uint(bp[(128 + col) * LDSW + c + 4]);
#pragma unroll
                for (int mt = 0; mt < 2; mt++)
                    mma_tf32(acc[mt][nt][0], acc[mt][nt][1], acc[mt][nt][2], acc[mt][nt][3],
                             a[mt][0], a[mt][1], a[mt][2], a[mt][3], b0, b1);
            }
        }
        __syncthreads();
        if (it + 1 < NT) stsB(s ^ 1);
    }

    float sce = s2[e];
#pragma unroll
    for (int mt = 0; mt < 2; mt++) {
#pragma unroll
        for (int half = 0; half < 2; half++) {
            int row = rm + mt * 16 + (L >> 2) + half * 8;
            int m   = m0 + row;
            if (m >= end) continue;
            int   slot = g_slot[m];
            float wv   = g_wt[m] * sce;
            float* yp  = g_Y + (size_t)slot * DD + n0;
#pragma unroll
            for (int nt = 0; nt < 8; nt++) {
                int col = cn + nt * 8 + (L & 3) * 2;
                *reinterpret_cast<float2*>(yp + col) =
                    make_float2(wv * acc[mt][nt][half * 2 + 0],
                                wv * acc[mt][nt][half * 2 + 1]);
            }
        }
    }
}

// ---------------- pass 3: out[t] = sum_k Y[t*6+k] ---------------------------
__global__ void k_reduce(float* __restrict__ out) {
    int i = blockIdx.x * blockDim.x + threadIdx.x;
    int t  = i / (DD / 4);
    int d4 = (i % (DD / 4)) * 4;
    const float* base = g_Y + (size_t)t * KSLOT * DD + d4;
    float4 acc = make_float4(0.f, 0.f, 0.f, 0.f);
#pragma unroll
    for (int k = 0; k < KSLOT; k++) {
        float4 v = *reinterpret_cast<const float4*>(base + (size_t)k * DD);
        acc.x += v.x; acc.y += v.y; acc.z += v.z; acc.w += v.w;
    }
    *reinterpret_cast<float4*>(out + (size_t)t * DD + d4) = acc;
}

// ---------------- launch ----------------------------------------------------
extern "C" void kernel_launch(void* const* d_in, const int* in_sizes, int n_in,
                              void* d_out, int out_size) {
    const float* x  = (const float*)d_in[0];
    const float* w0 = (const float*)d_in[1];
    const float* w1 = (const float*)d_in[2];
    const float* w2 = (const float*)d_in[3];
    const float* s0 = (const float*)d_in[4];
    const float* s1 = (const float*)d_in[5];
    const float* s2 = (const float*)d_in[6];
    const int*   se = (const int*)d_in[7];
    const float* rw = (const float*)d_in[8];
    float* out = (float*)d_out;

    k_route<<<1, 1024>>>(se, rw);

    dim3 g1(MAXTILES, DFF / 64);
    k_gateup<<<g1, 256>>>(x, w0, w1, s0, s1);

    dim3 g2(MAXTILES, DD / 128);
    k_down<<<g2, 256>>>(w2, s2);

    k_reduce<<<(TT * DD / 4) / 256, 256>>>(out);
}

// round 8
// speedup vs baseline: 1.1665x; 1.1665x over previous
#include <cuda_runtime.h>
#include <math.h>
#include <stdint.h>

#define TT    1024
#define DD    2048
#define DFF   1024
#define EE    16
#define KSLOT 6
#define TK    (TT*KSLOT)
#define MAXTILES 64
#define KT    32
#define LDSW  40   // smem row stride (words); row->row bank shift 8 -> conflict-free

// ---------------- scratch (device globals; no allocations allowed) ----------
__device__ int   g_off[EE + 1];
__device__ int   g_tok[TK];
__device__ int   g_slot[TK];
__device__ float g_wt[TK];
__device__ int   g_tile_e[MAXTILES];
__device__ int   g_tile_m0[MAXTILES];
__device__ int   g_ntiles;
__device__ __align__(16) float g_X[(size_t)TT * DD];            // tf32-rounded x
__device__ __align__(16) float g_H[(size_t)(TK + 128) * DFF];   // tf32-rounded h
__device__ __align__(16) float g_Y[(size_t)TK * DD];

// ---------------- helpers ----------------------------------------------------
__device__ __forceinline__ uint32_t f2tf(float f) {
    uint32_t u;
    asm("cvt.rna.tf32.f32 %0, %1;" : "=r"(u) : "f"(f));
    return u;
}

__device__ __forceinline__ void mma_tf32(float& d0, float& d1, float& d2, float& d3,
                                         uint32_t a0, uint32_t a1, uint32_t a2, uint32_t a3,
                                         uint32_t b0, uint32_t b1) {
    asm volatile(
        "mma.sync.aligned.m16n8k8.row.col.f32.tf32.tf32.f32 "
        "{%0,%1,%2,%3},{%4,%5,%6,%7},{%8,%9},{%0,%1,%2,%3};"
        : "+f"(d0), "+f"(d1), "+f"(d2), "+f"(d3)
        : "r"(a0), "r"(a1), "r"(a2), "r"(a3), "r"(b0), "r"(b1));
}

__device__ __forceinline__ void cp16(void* smem_dst, const void* gmem_src) {
    unsigned d = (unsigned)__cvta_generic_to_shared(smem_dst);
    asm volatile("cp.async.cg.shared.global [%0], [%1], 16;" :: "r"(d), "l"(gmem_src));
}
#define CP_COMMIT() asm volatile("cp.async.commit_group;")
#define CP_WAIT1()  asm volatile("cp.async.wait_group 1;")

// ---------------- prep: g_X = rna_tf32(x) -----------------------------------
__global__ void k_prep(const float* __restrict__ x) {
    int i = (blockIdx.x * blockDim.x + threadIdx.x) * 4;
    float4 v = *reinterpret_cast<const float4*>(x + i);
    *reinterpret_cast<uint4*>(g_X + i) =
        make_uint4(f2tf(v.x), f2tf(v.y), f2tf(v.z), f2tf(v.w));
}

// ---------------- routing: one CTA does count+scan+scatter ------------------
__global__ void k_route(const int* __restrict__ se, const float* __restrict__ rw) {
    __shared__ int cnt[EE], cur[EE], off[EE + 1];
    int tid = threadIdx.x;
    if (tid < EE) { cnt[tid] = 0; cur[tid] = 0; }
    __syncthreads();
    for (int i = tid; i < TK; i += 1024) atomicAdd(&cnt[se[i] & (EE - 1)], 1);
    __syncthreads();
    if (tid == 0) {
        int s = 0, nt = 0;
        off[0] = 0; g_off[0] = 0;
        for (int e = 0; e < EE; e++) {
            int o = s;
            s += cnt[e];
            off[e + 1] = s; g_off[e + 1] = s;
            for (int m0 = o; m0 < s; m0 += 128) {
                g_tile_e[nt] = e; g_tile_m0[nt] = m0; nt++;
            }
        }
        g_ntiles = nt;
    }
    __syncthreads();
    for (int i = tid; i < TK; i += 1024) {
        int e = se[i] & (EE - 1);
        int p = off[e] + atomicAdd(&cur[e], 1);
        g_tok[p]  = i / KSLOT;
        g_slot[p] = i;
        g_wt[p]   = rw[i];
    }
}

// ---------------- pass 1: H = silu(x@w0^T*s0) * (x@w1^T*s1) -----------------
// 128(M) x 64(N dff) tile, gate+up; 8 warps = 4(M) x 2(N); warp 32x32 per mat.
// Buffer rows: A 0-127, Bg 128-191, Bu 192-255. cp.async KT=32 double buffer.
// A already tf32 (g_X): no cvt. Fragment pairs via LDS.64 (K relabeled).
#define P1_SMEM (2*256*LDSW*4 + 512)

__global__ __launch_bounds__(256, 2)
void k_gateup(const float* __restrict__ w0,
              const float* __restrict__ w1,
              const float* __restrict__ s0,
              const float* __restrict__ s1) {
    int tile = blockIdx.x;
    if (tile >= g_ntiles) return;
    int e   = g_tile_e[tile];
    int m0  = g_tile_m0[tile];
    int end = g_off[e + 1];
    int n0  = blockIdx.y * 64;

    extern __shared__ __align__(16) float sm[];
    float (*buf)[256 * LDSW] = (float(*)[256 * LDSW])sm;
    int* toks = (int*)(sm + 2 * 256 * LDSW);

    int tid = threadIdx.x;
    if (tid < 128) {
        int m = m0 + tid;
        toks[tid] = (m < end) ? g_tok[m] : 0;
    }
    __syncthreads();

    const float* w0e = w0 + (size_t)e * DFF * DD;
    const float* w1e = w1 + (size_t)e * DFF * DD;

    auto prefetch = [&](int s, int k0) {
        float* b = buf[s];
#pragma unroll
        for (int i = 0; i < 4; i++) {
            int lin = tid + i * 256, row = lin >> 3, c4 = (lin & 7) * 4;
            cp16(b + row * LDSW + c4, g_X + (size_t)toks[row] * DD + k0 + c4);
        }
#pragma unroll
        for (int i = 0; i < 2; i++) {
            int lin = tid + i * 256, row = lin >> 3, c4 = (lin & 7) * 4;
            size_t boff = (size_t)(n0 + row) * DD + k0 + c4;
            cp16(b + (128 + row) * LDSW + c4, w0e + boff);
            cp16(b + (192 + row) * LDSW + c4, w1e + boff);
        }
    };

    int w  = tid >> 5, L = tid & 31;
    int wm = w & 3, wn = w >> 2;
    int rm = wm * 32, cn = wn * 32;
    int cw = 2 * (L & 3);          // column-pair base within kk group

    float accg[2][4][4] = {}, accu[2][4][4] = {};

    const int NT = DD / KT;   // 64
    prefetch(0, 0);
    CP_COMMIT();

    for (int it = 0; it < NT; it++) {
        if (it + 1 < NT) prefetch((it + 1) & 1, (it + 1) * KT);
        CP_COMMIT();
        CP_WAIT1();
        __syncthreads();
        const float* bp = buf[it & 1];

#pragma unroll
        for (int kk = 0; kk < KT; kk += 8) {
            uint32_t a[2][4];
#pragma unroll
            for (int mt = 0; mt < 2; mt++) {
                int r = rm + mt * 16 + (L >> 2);
                float2 lo = *reinterpret_cast<const float2*>(bp + r * LDSW + kk + cw);
                float2 hi = *reinterpret_cast<const float2*>(bp + (r + 8) * LDSW + kk + cw);
                a[mt][0] = __float_as_uint(lo.x);
                a[mt][1] = __float_as_uint(hi.x);
                a[mt][2] = __float_as_uint(lo.y);
                a[mt][3] = __float_as_uint(hi.y);
            }
#pragma unroll
            for (int nt = 0; nt < 4; nt++) {
                int col = cn + nt * 8 + (L >> 2);
                float2 gg = *reinterpret_cast<const float2*>(bp + (128 + col) * LDSW + kk + cw);
                float2 uu = *reinterpret_cast<const float2*>(bp + (192 + col) * LDSW + kk + cw);
                uint32_t bg0 = f2tf(gg.x), bg1 = f2tf(gg.y);
                uint32_t bu0 = f2tf(uu.x), bu1 = f2tf(uu.y);
#pragma unroll
                for (int mt = 0; mt < 2; mt++) {
                    mma_tf32(accg[mt][nt][0], accg[mt][nt][1], accg[mt][nt][2], accg[mt][nt][3],
                             a[mt][0], a[mt][1], a[mt][2], a[mt][3], bg0, bg1);
                    mma_tf32(accu[mt][nt][0], accu[mt][nt][1], accu[mt][nt][2], accu[mt][nt][3],
                             a[mt][0], a[mt][1], a[mt][2], a[mt][3], bu0, bu1);
                }
            }
        }
        __syncthreads();
    }

    // SwiGLU epilogue; store h pre-rounded tf32 (pass2 A then needs no cvt)
    float sc0 = s0[e], sc1 = s1[e];
#pragma unroll
    for (int mt = 0; mt < 2; mt++) {
#pragma unroll
        for (int half = 0; half < 2; half++) {
            int row = rm + mt * 16 + (L >> 2) + half * 8;
            int m   = m0 + row;
            if (m >= end) continue;
#pragma unroll
            for (int nt = 0; nt < 4; nt++) {
                int col = cn + nt * 8 + (L & 3) * 2;
                float gv0 = accg[mt][nt][half * 2 + 0] * sc0;
                float gv1 = accg[mt][nt][half * 2 + 1] * sc0;
                float uv0 = accu[mt][nt][half * 2 + 0] * sc1;
                float uv1 = accu[mt][nt][half * 2 + 1] * sc1;
                float h0 = (gv0 / (1.f + expf(-gv0))) * uv0;
                float h1 = (gv1 / (1.f + expf(-gv1))) * uv1;
                *reinterpret_cast<float2*>(g_H + (size_t)m * DFF + n0 + col) =
                    make_float2(__uint_as_float(f2tf(h0)), __uint_as_float(f2tf(h1)));
            }
        }
    }
}

// ---------------- pass 2: Y[slot] = wt*s2 * (H @ w2^T) ----------------------
// 128x128 tile; 8 warps = 4(M) x 2(N); warp 32x64. Buffer rows: A 0-127, B 128-255.
// A (g_H, pre-rounded) no cvt; B (w2) cvt at fragment load.
#define P2_SMEM (2*256*LDSW*4)

__global__ __launch_bounds__(256, 2)
void k_down(const float* __restrict__ w2,
            const float* __restrict__ s2) {
    int tile = blockIdx.x;
    if (tile >= g_ntiles) return;
    int e   = g_tile_e[tile];
    int m0  = g_tile_m0[tile];
    int end = g_off[e + 1];
    int n0  = blockIdx.y * 128;

    extern __shared__ __align__(16) float sm[];
    float (*buf)[256 * LDSW] = (float(*)[256 * LDSW])sm;

    int tid = threadIdx.x;
    const float* w2e = w2 + (size_t)e * DD * DFF;

    auto prefetch = [&](int s, int k0) {
        float* b = buf[s];
#pragma unroll
        for (int i = 0; i < 4; i++) {
            int lin = tid + i * 256, row = lin >> 3, c4 = (lin & 7) * 4;
            cp16(b + row * LDSW + c4,         g_H + (size_t)(m0 + row) * DFF + k0 + c4);
            cp16(b + (128 + row) * LDSW + c4, w2e + (size_t)(n0 + row) * DFF + k0 + c4);
        }
    };

    int w  = tid >> 5, L = tid & 31;
    int wm = w & 3, wn = w >> 2;
    int rm = wm * 32, cn = wn * 64;
    int cw = 2 * (L & 3);

    float acc[2][8][4] = {};

    const int NT = DFF / KT;   // 32
    prefetch(0, 0);
    CP_COMMIT();

    for (int it = 0; it < NT; it++) {
        if (it + 1 < NT) prefetch((it + 1) & 1, (it + 1) * KT);
        CP_COMMIT();
        CP_WAIT1();
        __syncthreads();
        const float* bp = buf[it & 1];

#pragma unroll
        for (int kk = 0; kk < KT; kk += 8) {
            uint32_t a[2][4];
#pragma unroll
            for (int mt = 0; mt < 2; mt++) {
                int r = rm + mt * 16 + (L >> 2);
                float2 lo = *reinterpret_cast<const float2*>(bp + r * LDSW + kk + cw);
                float2 hi = *reinterpret_cast<const float2*>(bp + (r + 8) * LDSW + kk + cw);
                a[mt][0] = __float_as_uint(lo.x);
                a[mt][1] = __float_as_uint(hi.x);
                a[mt][2] = __float_as_uint(lo.y);
                a[mt][3] = __float_as_uint(hi.y);
            }
#pragma unroll
            for (int nt = 0; nt < 8; nt++) {
                int col = cn + nt * 8 + (L >> 2);
                float2 bb = *reinterpret_cast<const float2*>(bp + (128 + col) * LDSW + kk + cw);
                uint32_t b0 = f2tf(bb.x), b1 = f2tf(bb.y);
#pragma unroll
                for (int mt = 0; mt < 2; mt++)
                    mma_tf32(acc[mt][nt][0], acc[mt][nt][1], acc[mt][nt][2], acc[mt][nt][3],
                             a[mt][0], a[mt][1], a[mt][2], a[mt][3], b0, b1);
            }
        }
        __syncthreads();
    }

    float sce = s2[e];
#pragma unroll
    for (int mt = 0; mt < 2; mt++) {
#pragma unroll
        for (int half = 0; half < 2; half++) {
            int row = rm + mt * 16 + (L >> 2) + half * 8;
            int m   = m0 + row;
            if (m >= end) continue;
            int   slot = g_slot[m];
            float wv   = g_wt[m] * sce;
            float* yp  = g_Y + (size_t)slot * DD + n0;
#pragma unroll
            for (int nt = 0; nt < 8; nt++) {
                int col = cn + nt * 8 + (L & 3) * 2;
                *reinterpret_cast<float2*>(yp + col) =
                    make_float2(wv * acc[mt][nt][half * 2 + 0],
                                wv * acc[mt][nt][half * 2 + 1]);
            }
        }
    }
}

// ---------------- pass 3: out[t] = sum_k Y[t*6+k] ---------------------------
__global__ void k_reduce(float* __restrict__ out) {
    int i = blockIdx.x * blockDim.x + threadIdx.x;
    int t  = i / (DD / 4);
    int d4 = (i % (DD / 4)) * 4;
    const float* base = g_Y + (size_t)t * KSLOT * DD + d4;
    float4 acc = make_float4(0.f, 0.f, 0.f, 0.f);
#pragma unroll
    for (int k = 0; k < KSLOT; k++) {
        float4 v = *reinterpret_cast<const float4*>(base + (size_t)k * DD);
        acc.x += v.x; acc.y += v.y; acc.z += v.z; acc.w += v.w;
    }
    *reinterpret_cast<float4*>(out + (size_t)t * DD + d4) = acc;
}

// ---------------- launch ----------------------------------------------------
extern "C" void kernel_launch(void* const* d_in, const int* in_sizes, int n_in,
                              void* d_out, int out_size) {
    const float* x  = (const float*)d_in[0];
    const float* w0 = (const float*)d_in[1];
    const float* w1 = (const float*)d_in[2];
    const float* w2 = (const float*)d_in[3];
    const float* s0 = (const float*)d_in[4];
    const float* s1 = (const float*)d_in[5];
    const float* s2 = (const float*)d_in[6];
    const int*   se = (const int*)d_in[7];
    const float* rw = (const float*)d_in[8];
    float* out = (float*)d_out;

    static bool attr_set = false;
    if (!attr_set) {
        cudaFuncSetAttribute(k_gateup, cudaFuncAttributeMaxDynamicSharedMemorySize, P1_SMEM);
        cudaFuncSetAttribute(k_down,   cudaFuncAttributeMaxDynamicSharedMemorySize, P2_SMEM);
        attr_set = true;
    }

    k_prep<<<(TT * DD / 4) / 256, 256>>>(x);
    k_route<<<1, 1024>>>(se, rw);

    dim3 g1(MAXTILES, DFF / 64);
    k_gateup<<<g1, 256, P1_SMEM>>>(w0, w1, s0, s1);

    dim3 g2(MAXTILES, DD / 128);
    k_down<<<g2, 256, P2_SMEM>>>(w2, s2);

    k_reduce<<<(TT * DD / 4) / 256, 256>>>(out);
}

// round 9
// speedup vs baseline: 1.2908x; 1.1066x over previous
#include <cuda_runtime.h>
#include <math.h>
#include <stdint.h>

#define TT    1024
#define DD    2048
#define DFF   1024
#define EE    16
#define KSLOT 6
#define TK    (TT*KSLOT)
#define MAXTILES 64
#define KT    32
#define LDSW  40   // smem row stride (words); row->row bank shift 8 -> conflict-free

// ---------------- scratch (device globals; no allocations allowed) ----------
__device__ int   g_off[EE + 1];
__device__ int   g_tok[TK];
__device__ int   g_slot[TK];
__device__ float g_wt[TK];
__device__ int   g_tile_e[MAXTILES];
__device__ int   g_tile_m0[MAXTILES];
__device__ int   g_ntiles;
__device__ __align__(16) float g_X[(size_t)TT * DD];            // tf32-rounded x
__device__ __align__(16) float g_H[(size_t)(TK + 128) * DFF];   // tf32-rounded h
__device__ __align__(16) float g_Y[(size_t)TK * DD];

// ---------------- helpers ----------------------------------------------------
__device__ __forceinline__ uint32_t f2tf(float f) {
    uint32_t u;
    asm("cvt.rna.tf32.f32 %0, %1;" : "=r"(u) : "f"(f));
    return u;
}

__device__ __forceinline__ void mma_tf32(float& d0, float& d1, float& d2, float& d3,
                                         uint32_t a0, uint32_t a1, uint32_t a2, uint32_t a3,
                                         uint32_t b0, uint32_t b1) {
    asm volatile(
        "mma.sync.aligned.m16n8k8.row.col.f32.tf32.tf32.f32 "
        "{%0,%1,%2,%3},{%4,%5,%6,%7},{%8,%9},{%0,%1,%2,%3};"
        : "+f"(d0), "+f"(d1), "+f"(d2), "+f"(d3)
        : "r"(a0), "r"(a1), "r"(a2), "r"(a3), "r"(b0), "r"(b1));
}

__device__ __forceinline__ void cp16(void* smem_dst, const void* gmem_src) {
    unsigned d = (unsigned)__cvta_generic_to_shared(smem_dst);
    asm volatile("cp.async.cg.shared.global [%0], [%1], 16;" :: "r"(d), "l"(gmem_src));
}
#define CP_COMMIT() asm volatile("cp.async.commit_group;")
#define CP_WAIT1()  asm volatile("cp.async.wait_group 1;")

// ---------------- prep: g_X = rna_tf32(x) -----------------------------------
__global__ void k_prep(const float* __restrict__ x) {
    int i = (blockIdx.x * blockDim.x + threadIdx.x) * 4;
    float4 v = *reinterpret_cast<const float4*>(x + i);
    *reinterpret_cast<uint4*>(g_X + i) =
        make_uint4(f2tf(v.x), f2tf(v.y), f2tf(v.z), f2tf(v.w));
}

// ---------------- routing: one CTA does count+scan+scatter ------------------
__global__ void k_route(const int* __restrict__ se, const float* __restrict__ rw) {
    __shared__ int cnt[EE], cur[EE], off[EE + 1];
    int tid = threadIdx.x;
    if (tid < EE) { cnt[tid] = 0; cur[tid] = 0; }
    __syncthreads();
    for (int i = tid; i < TK; i += 1024) atomicAdd(&cnt[se[i] & (EE - 1)], 1);
    __syncthreads();
    if (tid == 0) {
        int s = 0, nt = 0;
        off[0] = 0; g_off[0] = 0;
        for (int e = 0; e < EE; e++) {
            int o = s;
            s += cnt[e];
            off[e + 1] = s; g_off[e + 1] = s;
            for (int m0 = o; m0 < s; m0 += 128) {
                g_tile_e[nt] = e; g_tile_m0[nt] = m0; nt++;
            }
        }
        g_ntiles = nt;
    }
    __syncthreads();
    for (int i = tid; i < TK; i += 1024) {
        int e = se[i] & (EE - 1);
        int p = off[e] + atomicAdd(&cur[e], 1);
        g_tok[p]  = i / KSLOT;
        g_slot[p] = i;
        g_wt[p]   = rw[i];
    }
}

// ---------------- pass 1: H = silu(x@w0^T*s0) * (x@w1^T*s1) -----------------
// 128(M) x 64(N dff) tile, gate+up; 8 warps = 2(M) x 4(N); warp 64x16 per mat.
// Buffer rows: A 0-127, Bg 128-191, Bu 192-255. cp.async KT=32 double buffer.
#define P1_SMEM (2*256*LDSW*4 + 512)

__global__ __launch_bounds__(256, 2)
void k_gateup(const float* __restrict__ w0,
              const float* __restrict__ w1,
              const float* __restrict__ s0,
              const float* __restrict__ s1) {
    int tile = blockIdx.x;
    if (tile >= g_ntiles) return;
    int e   = g_tile_e[tile];
    int m0  = g_tile_m0[tile];
    int end = g_off[e + 1];
    int n0  = blockIdx.y * 64;

    extern __shared__ __align__(16) float sm[];
    float (*buf)[256 * LDSW] = (float(*)[256 * LDSW])sm;
    int* toks = (int*)(sm + 2 * 256 * LDSW);

    int tid = threadIdx.x;
    if (tid < 128) {
        int m = m0 + tid;
        toks[tid] = (m < end) ? g_tok[m] : 0;
    }
    __syncthreads();

    const float* w0e = w0 + (size_t)e * DFF * DD;
    const float* w1e = w1 + (size_t)e * DFF * DD;

    auto prefetch = [&](int s, int k0) {
        float* b = buf[s];
#pragma unroll
        for (int i = 0; i < 4; i++) {
            int lin = tid + i * 256, row = lin >> 3, c4 = (lin & 7) * 4;
            cp16(b + row * LDSW + c4, g_X + (size_t)toks[row] * DD + k0 + c4);
        }
#pragma unroll
        for (int i = 0; i < 2; i++) {
            int lin = tid + i * 256, row = lin >> 3, c4 = (lin & 7) * 4;
            size_t boff = (size_t)(n0 + row) * DD + k0 + c4;
            cp16(b + (128 + row) * LDSW + c4, w0e + boff);
            cp16(b + (192 + row) * LDSW + c4, w1e + boff);
        }
    };

    int w  = tid >> 5, L = tid & 31;
    int wm = w & 1, wn = w >> 1;       // 2(M) x 4(N)
    int rm = wm * 64, cn = wn * 16;
    int cw = 2 * (L & 3);              // column-pair base within kk group

    float accg[4][2][4] = {}, accu[4][2][4] = {};

    const int NT = DD / KT;   // 64
    prefetch(0, 0);
    CP_COMMIT();

    for (int it = 0; it < NT; it++) {
        if (it + 1 < NT) prefetch((it + 1) & 1, (it + 1) * KT);
        CP_COMMIT();
        CP_WAIT1();
        __syncthreads();
        const float* bp = buf[it & 1];

#pragma unroll
        for (int kk = 0; kk < KT; kk += 8) {
            uint32_t a[4][4];
#pragma unroll
            for (int mt = 0; mt < 4; mt++) {
                int r = rm + mt * 16 + (L >> 2);
                float2 lo = *reinterpret_cast<const float2*>(bp + r * LDSW + kk + cw);
                float2 hi = *reinterpret_cast<const float2*>(bp + (r + 8) * LDSW + kk + cw);
                a[mt][0] = __float_as_uint(lo.x);
                a[mt][1] = __float_as_uint(hi.x);
                a[mt][2] = __float_as_uint(lo.y);
                a[mt][3] = __float_as_uint(hi.y);
            }
#pragma unroll
            for (int nt = 0; nt < 2; nt++) {
                int col = cn + nt * 8 + (L >> 2);
                float2 gg = *reinterpret_cast<const float2*>(bp + (128 + col) * LDSW + kk + cw);
                float2 uu = *reinterpret_cast<const float2*>(bp + (192 + col) * LDSW + kk + cw);
                uint32_t bg0 = f2tf(gg.x), bg1 = f2tf(gg.y);
                uint32_t bu0 = f2tf(uu.x), bu1 = f2tf(uu.y);
#pragma unroll
                for (int mt = 0; mt < 4; mt++) {
                    mma_tf32(accg[mt][nt][0], accg[mt][nt][1], accg[mt][nt][2], accg[mt][nt][3],
                             a[mt][0], a[mt][1], a[mt][2], a[mt][3], bg0, bg1);
                    mma_tf32(accu[mt][nt][0], accu[mt][nt][1], accu[mt][nt][2], accu[mt][nt][3],
                             a[mt][0], a[mt][1], a[mt][2], a[mt][3], bu0, bu1);
                }
            }
        }
        __syncthreads();
    }

    // SwiGLU epilogue; store h pre-rounded tf32 (pass2 A then needs no cvt)
    float sc0 = s0[e], sc1 = s1[e];
#pragma unroll
    for (int mt = 0; mt < 4; mt++) {
#pragma unroll
        for (int half = 0; half < 2; half++) {
            int row = rm + mt * 16 + (L >> 2) + half * 8;
            int m   = m0 + row;
            if (m >= end) continue;
#pragma unroll
            for (int nt = 0; nt < 2; nt++) {
                int col = cn + nt * 8 + (L & 3) * 2;
                float gv0 = accg[mt][nt][half * 2 + 0] * sc0;
                float gv1 = accg[mt][nt][half * 2 + 1] * sc0;
                float uv0 = accu[mt][nt][half * 2 + 0] * sc1;
                float uv1 = accu[mt][nt][half * 2 + 1] * sc1;
                float h0 = (gv0 / (1.f + expf(-gv0))) * uv0;
                float h1 = (gv1 / (1.f + expf(-gv1))) * uv1;
                *reinterpret_cast<float2*>(g_H + (size_t)m * DFF + n0 + col) =
                    make_float2(__uint_as_float(f2tf(h0)), __uint_as_float(f2tf(h1)));
            }
        }
    }
}

// ---------------- pass 2: Y[slot] = wt*s2 * (H @ w2^T) ----------------------
// 128x128 tile; 8 warps = 2(M) x 4(N); warp 64x32. Buffer rows: A 0-127, B 128-255.
// A (g_H, pre-rounded) no cvt; B (w2) cvt at fragment load.
#define P2_SMEM (2*256*LDSW*4)

__global__ __launch_bounds__(256, 2)
void k_down(const float* __restrict__ w2,
            const float* __restrict__ s2) {
    int tile = blockIdx.x;
    if (tile >= g_ntiles) return;
    int e   = g_tile_e[tile];
    int m0  = g_tile_m0[tile];
    int end = g_off[e + 1];
    int n0  = blockIdx.y * 128;

    extern __shared__ __align__(16) float sm[];
    float (*buf)[256 * LDSW] = (float(*)[256 * LDSW])sm;

    int tid = threadIdx.x;
    const float* w2e = w2 + (size_t)e * DD * DFF;

    auto prefetch = [&](int s, int k0) {
        float* b = buf[s];
#pragma unroll
        for (int i = 0; i < 4; i++) {
            int lin = tid + i * 256, row = lin >> 3, c4 = (lin & 7) * 4;
            cp16(b + row * LDSW + c4,         g_H + (size_t)(m0 + row) * DFF + k0 + c4);
            cp16(b + (128 + row) * LDSW + c4, w2e + (size_t)(n0 + row) * DFF + k0 + c4);
        }
    };

    int w  = tid >> 5, L = tid & 31;
    int wm = w & 1, wn = w >> 1;       // 2(M) x 4(N)
    int rm = wm * 64, cn = wn * 32;
    int cw = 2 * (L & 3);

    float acc[4][4][4] = {};

    const int NT = DFF / KT;   // 32
    prefetch(0, 0);
    CP_COMMIT();

    for (int it = 0; it < NT; it++) {
        if (it + 1 < NT) prefetch((it + 1) & 1, (it + 1) * KT);
        CP_COMMIT();
        CP_WAIT1();
        __syncthreads();
        const float* bp = buf[it & 1];

#pragma unroll
        for (int kk = 0; kk < KT; kk += 8) {
            uint32_t a[4][4];
#pragma unroll
            for (int mt = 0; mt < 4; mt++) {
                int r = rm + mt * 16 + (L >> 2);
                float2 lo = *reinterpret_cast<const float2*>(bp + r * LDSW + kk + cw);
                float2 hi = *reinterpret_cast<const float2*>(bp + (r + 8) * LDSW + kk + cw);
                a[mt][0] = __float_as_uint(lo.x);
                a[mt][1] = __float_as_uint(hi.x);
                a[mt][2] = __float_as_uint(lo.y);
                a[mt][3] = __float_as_uint(hi.y);
            }
#pragma unroll
            for (int nt = 0; nt < 4; nt++) {
                int col = cn + nt * 8 + (L >> 2);
                float2 bb = *reinterpret_cast<const float2*>(bp + (128 + col) * LDSW + kk + cw);
                uint32_t b0 = f2tf(bb.x), b1 = f2tf(bb.y);
#pragma unroll
                for (int mt = 0; mt < 4; mt++)
                    mma_tf32(acc[mt][nt][0], acc[mt][nt][1], acc[mt][nt][2], acc[mt][nt][3],
                             a[mt][0], a[mt][1], a[mt][2], a[mt][3], b0, b1);
            }
        }
        __syncthreads();
    }

    float sce = s2[e];
#pragma unroll
    for (int mt = 0; mt < 4; mt++) {
#pragma unroll
        for (int half = 0; half < 2; half++) {
            int row = rm + mt * 16 + (L >> 2) + half * 8;
            int m   = m0 + row;
            if (m >= end) continue;
            int   slot = g_slot[m];
            float wv   = g_wt[m] * sce;
            float* yp  = g_Y + (size_t)slot * DD + n0;
#pragma unroll
            for (int nt = 0; nt < 4; nt++) {
                int col = cn + nt * 8 + (L & 3) * 2;
                *reinterpret_cast<float2*>(yp + col) =
                    make_float2(wv * acc[mt][nt][half * 2 + 0],
                                wv * acc[mt][nt][half * 2 + 1]);
            }
        }
    }
}

// ---------------- pass 3: out[t] = sum_k Y[t*6+k] ---------------------------
__global__ void k_reduce(float* __restrict__ out) {
    int i = blockIdx.x * blockDim.x + threadIdx.x;
    int t  = i / (DD / 4);
    int d4 = (i % (DD / 4)) * 4;
    const float* base = g_Y + (size_t)t * KSLOT * DD + d4;
    float4 acc = make_float4(0.f, 0.f, 0.f, 0.f);
#pragma unroll
    for (int k = 0; k < KSLOT; k++) {
        float4 v = *reinterpret_cast<const float4*>(base + (size_t)k * DD);
        acc.x += v.x; acc.y += v.y; acc.z += v.z; acc.w += v.w;
    }
    *reinterpret_cast<float4*>(out + (size_t)t * DD + d4) = acc;
}

// ---------------- launch ----------------------------------------------------
extern "C" void kernel_launch(void* const* d_in, const int* in_sizes, int n_in,
                              void* d_out, int out_size) {
    const float* x  = (const float*)d_in[0];
    const float* w0 = (const float*)d_in[1];
    const float* w1 = (const float*)d_in[2];
    const float* w2 = (const float*)d_in[3];
    const float* s0 = (const float*)d_in[4];
    const float* s1 = (const float*)d_in[5];
    const float* s2 = (const float*)d_in[6];
    const int*   se = (const int*)d_in[7];
    const float* rw = (const float*)d_in[8];
    float* out = (float*)d_out;

    static bool attr_set = false;
    if (!attr_set) {
        cudaFuncSetAttribute(k_gateup, cudaFuncAttributeMaxDynamicSharedMemorySize, P1_SMEM);
        cudaFuncSetAttribute(k_down,   cudaFuncAttributeMaxDynamicSharedMemorySize, P2_SMEM);
        attr_set = true;
    }

    k_prep<<<(TT * DD / 4) / 256, 256>>>(x);
    k_route<<<1, 1024>>>(se, rw);

    dim3 g1(MAXTILES, DFF / 64);
    k_gateup<<<g1, 256, P1_SMEM>>>(w0, w1, s0, s1);

    dim3 g2(MAXTILES, DD / 128);
    k_down<<<g2, 256, P2_SMEM>>>(w2, s2);

    k_reduce<<<(TT * DD / 4) / 256, 256>>>(out);
}